// round 15
// baseline (speedup 1.0000x reference)
#include <cuda_runtime.h>
#include <cuda_fp16.h>
#include <cstdint>

// ---------------------------------------------------------------------------
// KQEnergyBlock: B=8, N=1024, D=768, H=12, Z=64, HID=3072
//   [Q|K|hid] = x @ [Wq;Wk;Wmlp]^T  (ONE projection GEMM, epilogue routing)
//   FA1 (64-row tiles): S=Q K^T, Pu=exp(beta S), AV1=Zinv*(Pu K), Zinv inline
//   FA2: S^T, P'=exp(beta S^T)*Zinv[q] (Zinv folded into exp), AV2 = P' Q
//   out = [AV1|AV2|hid] @ [Wq;Wk;Wmlp]-stacked  (single K=4608 GEMM)
// R15: wprep fuses weight conv+transpose; qstrans eliminated.
// ---------------------------------------------------------------------------

namespace {
constexpr int Bc = 8, Nc = 1024, Dc = 768, Hc = 12, Zc = 64, HIDc = 3072;
constexpr int Mrows = Bc * Nc;    // 8192
constexpr int D2 = 2 * Dc;        // 1536
constexpr int KC = 2 * Dc + HIDc; // 4608
}

__device__ __align__(16) __half g_QKh[(size_t)Mrows * D2];      // [Q|K]
__device__ __align__(16) __half g_KTh[(size_t)Bc * Hc * Zc * Nc];
__device__ __align__(16) __half g_QTh[(size_t)Bc * Hc * Zc * Nc];
__device__ __align__(16) __half g_AVh[(size_t)Mrows * KC];      // [AV1|AV2|hid]
__device__ __align__(16) float  g_Zinv[(size_t)Bc * Hc * Nc];
__device__ __align__(16) __half g_xh[Mrows * Dc];
__device__ __align__(16) __half g_WcatH[(size_t)KC * Dc];       // rows: Wq|Wk|Wmlp
__device__ __align__(16) __half g_WallTh[(size_t)Dc * KC];      // [d][e|e'|h]

enum { E_STOREF = 0, E_PROJ = 1 };

__device__ __forceinline__ void cp_async16(void* smem_dst, const void* gmem_src) {
    uint32_t sa = (uint32_t)__cvta_generic_to_shared(smem_dst);
    asm volatile("cp.async.cg.shared.global [%0], [%1], 16;\n" :: "r"(sa), "l"(gmem_src));
}
__device__ __forceinline__ void cp_commit() {
    asm volatile("cp.async.commit_group;\n");
}
template <int Nw>
__device__ __forceinline__ void cp_wait() {
    asm volatile("cp.async.wait_group %0;\n" :: "n"(Nw));
}

__device__ __forceinline__ void mma_f16(float c[4],
                                        uint32_t a0, uint32_t a1, uint32_t a2, uint32_t a3,
                                        uint32_t b0, uint32_t b1) {
    asm volatile(
        "mma.sync.aligned.m16n8k16.row.col.f32.f16.f16.f32 "
        "{%0,%1,%2,%3}, {%4,%5,%6,%7}, {%8,%9}, {%0,%1,%2,%3};\n"
        : "+f"(c[0]), "+f"(c[1]), "+f"(c[2]), "+f"(c[3])
        : "r"(a0), "r"(a1), "r"(a2), "r"(a3), "r"(b0), "r"(b1));
}

// ===========================================================================
// Fused flash attention, 64 output rows per CTA, 256 threads / 8 warps.
// DO_ZINV=1 (FA1): compute rowsums -> Zinv, scale AV rows, write Zinv.
// DO_ZINV=0 (FA2): multiply exp by Zinv[q] (streamed column dim), staged via
// cp.async alongside the C/T2 tiles.
// ===========================================================================
namespace fa {
constexpr int OFF_R   = 0;
constexpr int OFF_C   = 8192;
constexpr int OFF_T2  = 73728;
constexpr int OFF_P   = 139264;
constexpr int OFF_RED = 172032;
constexpr int OFF_ZS  = 173056;
constexpr int OFF_ZT  = 173312;   // [4][128] float staged Zinv tiles (FA2)
constexpr int SMEM    = 175360;
}

template <int DO_ZINV>
__global__ __launch_bounds__(256, 1)
void fa_k(const __half* __restrict__ Rbase, int ldr,
          const __half* __restrict__ Cbase, int ldcc,
          const __half* __restrict__ T2base, __half* __restrict__ Outbase,
          int ldo, float* __restrict__ zinvg, const float* __restrict__ betas)
{
    extern __shared__ __align__(16) char smem[];
    __half (*Rt)[64][32]      = reinterpret_cast<__half(*)[64][32]>(smem + fa::OFF_R);
    __half (*Ct)[2][128][32]  = reinterpret_cast<__half(*)[2][128][32]>(smem + fa::OFF_C);
    __half (*T2)[4][64][32]   = reinterpret_cast<__half(*)[4][64][32]>(smem + fa::OFF_T2);
    __half (*P)[4][64][32]    = reinterpret_cast<__half(*)[4][64][32]>(smem + fa::OFF_P);
    float (*red)[64]          = reinterpret_cast<float(*)[64]>(smem + fa::OFF_RED);
    float* zs                 = reinterpret_cast<float*>(smem + fa::OFF_ZS);
    float (*Zt)[128]          = reinterpret_cast<float(*)[128]>(smem + fa::OFF_ZT);

    const int bh = blockIdx.y;
    const int b = bh / Hc, hi = bh % Hc;
    const int blk = blockIdx.x;
    const float beta = betas[hi];

    const __half* Rb = Rbase + ((long)b * Nc + blk * 64) * ldr + hi * Zc;
    const __half* Cb = Cbase + (long)b * Nc * ldcc + hi * Zc;
    const __half* T2b = T2base + (long)bh * Zc * Nc;
    __half* Outb = Outbase + ((long)b * Nc + blk * 64) * ldo + hi * Zc;

    const int tid = threadIdx.x;
    const int warp = tid >> 5;
    const int lane = tid & 31;
    const int group = lane >> 2;
    const int tg = lane & 3;
    const int wq = warp >> 2;
    const int wk = warp & 3;

    auto loadC = [&](int it2, int s) {
#pragma unroll
        for (int i = 0; i < 4; i++) {
            int c = tid + i * 256;
            int m = c >> 3, r = c & 7;
            int zc = r >> 2, q = r & 3;
            cp_async16(&Ct[s][zc][m][q * 8],
                       &Cb[(long)(it2 * 128 + m) * ldcc + zc * 32 + q * 8]);
        }
#pragma unroll
        for (int i = 0; i < 4; i++) {
            int c = tid + i * 256;
            int kc = c >> 8, rem = c & 255;
            int z = rem >> 2, q = rem & 3;
            cp_async16(&T2[s][kc][z][q * 8],
                       &T2b[(long)z * Nc + it2 * 128 + kc * 32 + q * 8]);
        }
        if (DO_ZINV == 0) {
            if (tid < 32)
                cp_async16(&Zt[s][tid * 4],
                           &zinvg[(long)bh * Nc + it2 * 128 + tid * 4]);
        }
        cp_commit();
    };

    {
#pragma unroll
        for (int i = 0; i < 2; i++) {
            int c = tid + i * 256;
            int m = c >> 3, r = c & 7;
            int zc = r >> 2, q = r & 3;
            cp_async16(&Rt[zc][m][q * 8], &Rb[(long)m * ldr + zc * 32 + q * 8]);
        }
        loadC(0, 0);
        loadC(1, 1);
    }

    float av[2][2][4];
#pragma unroll
    for (int i = 0; i < 2; i++)
#pragma unroll
        for (int j = 0; j < 2; j++)
#pragma unroll
            for (int r = 0; r < 4; r++) av[i][j][r] = 0.f;
    float rs[2][2];
    if (DO_ZINV) {
#pragma unroll
        for (int i = 0; i < 2; i++) { rs[i][0] = 0.f; rs[i][1] = 0.f; }
    }

    for (int it = 0; it < 8; it++) {
        const int s = it & 3;
        if (it + 2 < 8) loadC(it + 2, (it + 2) & 3);
        else cp_commit();
        cp_wait<2>();
        __syncthreads();

        float sacc[2][4][4];
#pragma unroll
        for (int i = 0; i < 2; i++)
#pragma unroll
            for (int j = 0; j < 4; j++)
#pragma unroll
                for (int r = 0; r < 4; r++) sacc[i][j][r] = 0.f;

#pragma unroll
        for (int zc = 0; zc < 2; zc++) {
            uint4 a[2][2];
#pragma unroll
            for (int mt = 0; mt < 2; mt++) {
                int mr = wq * 32 + mt * 16 + group;
                a[mt][0] = *reinterpret_cast<const uint4*>(&Rt[zc][mr][tg * 8]);
                a[mt][1] = *reinterpret_cast<const uint4*>(&Rt[zc][mr + 8][tg * 8]);
            }
#pragma unroll
            for (int nt = 0; nt < 4; nt++) {
                int nc = wk * 32 + nt * 8 + group;
                uint4 bb = *reinterpret_cast<const uint4*>(&Ct[s][zc][nc][tg * 8]);
#pragma unroll
                for (int mt = 0; mt < 2; mt++) {
                    mma_f16(sacc[mt][nt], a[mt][0].x, a[mt][1].x, a[mt][0].y, a[mt][1].y,
                            bb.x, bb.y);
                    mma_f16(sacc[mt][nt], a[mt][0].z, a[mt][1].z, a[mt][0].w, a[mt][1].w,
                            bb.z, bb.w);
                }
            }
        }

        const int pcur = it & 1;
        const int pprev = pcur ^ 1;
        const int sprev = (it + 3) & 3;

#pragma unroll
        for (int j = 0; j < 4; j++) {
            if (it > 0) {
                uint4 a[2][2];
#pragma unroll
                for (int mt = 0; mt < 2; mt++) {
                    int mr = wq * 32 + mt * 16 + group;
                    a[mt][0] = *reinterpret_cast<const uint4*>(&P[pprev][j][mr][tg * 8]);
                    a[mt][1] = *reinterpret_cast<const uint4*>(&P[pprev][j][mr + 8][tg * 8]);
                }
#pragma unroll
                for (int nt = 0; nt < 2; nt++) {
                    int nc = wk * 16 + nt * 8 + group;
                    uint4 bb = *reinterpret_cast<const uint4*>(&T2[sprev][j][nc][tg * 8]);
#pragma unroll
                    for (int mt = 0; mt < 2; mt++) {
                        mma_f16(av[mt][nt], a[mt][0].x, a[mt][1].x, a[mt][0].y, a[mt][1].y,
                                bb.x, bb.y);
                        mma_f16(av[mt][nt], a[mt][0].z, a[mt][1].z, a[mt][0].w, a[mt][1].w,
                                bb.z, bb.w);
                    }
                }
            }
#pragma unroll
            for (int mt = 0; mt < 2; mt++) {
                int r0 = wq * 32 + mt * 16 + group;
                int colw = j * 8 + tg * 2;   // column within this warp's key-quarter
                float v0 = __expf(beta * sacc[mt][j][0]);
                float v1 = __expf(beta * sacc[mt][j][1]);
                float v2 = __expf(beta * sacc[mt][j][2]);
                float v3 = __expf(beta * sacc[mt][j][3]);
                if (DO_ZINV) {
                    rs[mt][0] += v0 + v1; rs[mt][1] += v2 + v3;
                } else {
                    // FA2: fold Zinv[q] (q = streamed column) into P
                    float z0 = Zt[s][wk * 32 + colw];
                    float z1 = Zt[s][wk * 32 + colw + 1];
                    v0 *= z0; v1 *= z1; v2 *= z0; v3 *= z1;
                }
                *reinterpret_cast<__half2*>(&P[pcur][wk][r0][colw]) =
                    __floats2half2_rn(v0, v1);
                *reinterpret_cast<__half2*>(&P[pcur][wk][r0 + 8][colw]) =
                    __floats2half2_rn(v2, v3);
            }
        }
        __syncthreads();
    }

    // epilogue: AV(7)
#pragma unroll
    for (int j = 0; j < 4; j++) {
        uint4 a[2][2];
#pragma unroll
        for (int mt = 0; mt < 2; mt++) {
            int mr = wq * 32 + mt * 16 + group;
            a[mt][0] = *reinterpret_cast<const uint4*>(&P[1][j][mr][tg * 8]);
            a[mt][1] = *reinterpret_cast<const uint4*>(&P[1][j][mr + 8][tg * 8]);
        }
#pragma unroll
        for (int nt = 0; nt < 2; nt++) {
            int nc = wk * 16 + nt * 8 + group;
            uint4 bb = *reinterpret_cast<const uint4*>(&T2[3][j][nc][tg * 8]);
#pragma unroll
            for (int mt = 0; mt < 2; mt++) {
                mma_f16(av[mt][nt], a[mt][0].x, a[mt][1].x, a[mt][0].y, a[mt][1].y,
                        bb.x, bb.y);
                mma_f16(av[mt][nt], a[mt][0].z, a[mt][1].z, a[mt][0].w, a[mt][1].w,
                        bb.z, bb.w);
            }
        }
    }

    if (DO_ZINV) {
#pragma unroll
        for (int mt = 0; mt < 2; mt++) {
#pragma unroll
            for (int h = 0; h < 2; h++) {
                float v = rs[mt][h];
                v += __shfl_xor_sync(0xffffffffu, v, 1);
                v += __shfl_xor_sync(0xffffffffu, v, 2);
                if (tg == 0)
                    red[wk][wq * 32 + mt * 16 + h * 8 + group] = v;
            }
        }
        __syncthreads();
        if (tid < 64) {
            float ssum = red[0][tid] + red[1][tid] + red[2][tid] + red[3][tid];
            float zi = 1.f / ssum;
            zs[tid] = zi;
            zinvg[(long)bh * Nc + blk * 64 + tid] = zi;
        }
        __syncthreads();
    }

#pragma unroll
    for (int mt = 0; mt < 2; mt++) {
#pragma unroll
        for (int nt = 0; nt < 2; nt++) {
            int col = wk * 16 + nt * 8 + tg * 2;
#pragma unroll
            for (int h = 0; h < 2; h++) {
                int row = wq * 32 + mt * 16 + h * 8 + group;
                float v0 = av[mt][nt][h * 2 + 0];
                float v1 = av[mt][nt][h * 2 + 1];
                if (DO_ZINV) {
                    float zi = zs[row];
                    v0 *= zi; v1 *= zi;
                }
                *reinterpret_cast<__half2*>(&Outb[(long)row * ldo + col]) =
                    __floats2half2_rn(v0, v1);
            }
        }
    }
}

// ===========================================================================
// Dense half GEMM, BK=64 chunked (R13, proven).
// ===========================================================================
template <int BM, int BN, int WM, int WN, int EPI>
__global__ __launch_bounds__((BM / WM) * (BN / WN) * 32)
void gemm_h(const __half* __restrict__ A, const __half* __restrict__ Bm,
            void* __restrict__ Cbase, void* __restrict__ C2base,
            int K, int lda, int ldb, int ldc)
{
    constexpr int BK = 64;
    constexpr int NW = (BM / WM) * (BN / WN);
    constexpr int NT = NW * 32;
    constexpr int MT = WM / 16;
    constexpr int NTI = WN / 8;
    constexpr int NST = 3;

    extern __shared__ __align__(16) __half dsm[];
    __half (*As)[2][BM][32] = reinterpret_cast<__half(*)[2][BM][32]>(dsm);
    __half (*Bs)[2][BN][32] =
        reinterpret_cast<__half(*)[2][BN][32]>(dsm + (size_t)NST * 2 * BM * 32);

    const int t = threadIdx.x;
    const int warp = t >> 5;
    const int lane = t & 31;
    const int group = lane >> 2;
    const int tg = lane & 3;
    const int wm = warp / (BN / WN);
    const int wn = warp % (BN / WN);
    const int m0 = blockIdx.y * BM;
    const int n0 = blockIdx.x * BN;

    const int nk = K / BK;

    auto prefetch = [&](int kt, int s) {
        const int k0 = kt * BK;
#pragma unroll
        for (int ch = 0; ch < 2; ch++) {
#pragma unroll
            for (int it = 0; it < (BM * 4) / NT; ++it) {
                int c = t + it * NT;
                int m = c >> 2, q = c & 3;
                cp_async16(&As[s][ch][m][q * 8],
                           &A[(long)(m0 + m) * lda + k0 + ch * 32 + q * 8]);
            }
#pragma unroll
            for (int it = 0; it < (BN * 4) / NT; ++it) {
                int c = t + it * NT;
                int n = c >> 2, q = c & 3;
                cp_async16(&Bs[s][ch][n][q * 8],
                           &Bm[(long)(n0 + n) * ldb + k0 + ch * 32 + q * 8]);
            }
        }
        cp_commit();
    };

    float acc[MT][NTI][4];
#pragma unroll
    for (int i = 0; i < MT; i++)
#pragma unroll
        for (int j = 0; j < NTI; j++)
#pragma unroll
            for (int r = 0; r < 4; r++) acc[i][j][r] = 0.f;

    prefetch(0, 0);
    if (nk > 1) prefetch(1, 1); else cp_commit();

    for (int kt = 0; kt < nk; kt++) {
        const int s = kt % NST;
        if (kt + 2 < nk) prefetch(kt + 2, (kt + 2) % NST);
        else cp_commit();
        cp_wait<2>();
        __syncthreads();

#pragma unroll
        for (int ch = 0; ch < 2; ch++) {
            uint4 a4[MT][2];
            uint4 b4[NTI];
#pragma unroll
            for (int mt = 0; mt < MT; mt++) {
                int mr = wm * WM + mt * 16 + group;
                a4[mt][0] = *reinterpret_cast<const uint4*>(&As[s][ch][mr][tg * 8]);
                a4[mt][1] = *reinterpret_cast<const uint4*>(&As[s][ch][mr + 8][tg * 8]);
            }
#pragma unroll
            for (int nt = 0; nt < NTI; nt++) {
                int nc = wn * WN + nt * 8 + group;
                b4[nt] = *reinterpret_cast<const uint4*>(&Bs[s][ch][nc][tg * 8]);
            }
#pragma unroll
            for (int mt = 0; mt < MT; mt++)
#pragma unroll
                for (int nt = 0; nt < NTI; nt++)
                    mma_f16(acc[mt][nt], a4[mt][0].x, a4[mt][1].x, a4[mt][0].y, a4[mt][1].y,
                            b4[nt].x, b4[nt].y);
#pragma unroll
            for (int mt = 0; mt < MT; mt++)
#pragma unroll
                for (int nt = 0; nt < NTI; nt++)
                    mma_f16(acc[mt][nt], a4[mt][0].z, a4[mt][1].z, a4[mt][0].w, a4[mt][1].w,
                            b4[nt].z, b4[nt].w);
        }
        __syncthreads();
    }

#pragma unroll
    for (int mt = 0; mt < MT; mt++) {
#pragma unroll
        for (int nt = 0; nt < NTI; nt++) {
            int gm = m0 + wm * WM + mt * 16 + group;
            int gn = n0 + wn * WN + nt * 8 + tg * 2;
#pragma unroll
            for (int half = 0; half < 2; half++) {
                int row = gm + half * 8;
                float v0 = acc[mt][nt][half * 2 + 0];
                float v1 = acc[mt][nt][half * 2 + 1];
                if (EPI == E_PROJ) {
                    if (gn < D2) {
                        __half* C = (__half*)Cbase;
                        *reinterpret_cast<__half2*>(&C[(long)row * D2 + gn]) =
                            __floats2half2_rn(v0, v1);
                    } else {
                        v0 = fmaxf(v0, 0.f); v1 = fmaxf(v1, 0.f);
                        __half* C2 = (__half*)C2base;
                        *reinterpret_cast<__half2*>(&C2[(long)row * KC + gn]) =
                            __floats2half2_rn(v0, v1);
                    }
                } else {
                    float* C = (float*)Cbase;
                    float2 w; w.x = v0; w.y = v1;
                    *reinterpret_cast<float2*>(&C[(long)row * ldc + gn]) = w;
                }
            }
        }
    }
}

// ===========================================================================
// Pre-pass kernels
// ===========================================================================
__global__ __launch_bounds__(256) void hconv_k(const float* __restrict__ src,
                                               __half* __restrict__ dst, long n4)
{
    long i = (long)blockIdx.x * 256 + threadIdx.x;
    if (i >= n4) return;
    float4 v = reinterpret_cast<const float4*>(src)[i];
    __half2 h0 = __floats2half2_rn(v.x, v.y);
    __half2 h1 = __floats2half2_rn(v.z, v.w);
    uint2 u;
    u.x = *reinterpret_cast<uint32_t*>(&h0);
    u.y = *reinterpret_cast<uint32_t*>(&h1);
    reinterpret_cast<uint2*>(dst)[i] = u;
}

// Weight prep: read float W[R][C] once; write half row-major copy (ld C) AND
// half transposed copy dallT[c*dld + r].
__global__ __launch_bounds__(256) void wprep_k(const float* __restrict__ src,
                                               __half* __restrict__ dcat,
                                               __half* __restrict__ dallT,
                                               int R, int C, int dld)
{
    __shared__ float tile[32][33];
    int c0 = blockIdx.x * 32, r0 = blockIdx.y * 32;
    int tx = threadIdx.x & 31, ty = threadIdx.x >> 5;
    for (int i = ty; i < 32; i += 8) {
        float v = src[(long)(r0 + i) * C + c0 + tx];
        tile[i][tx] = v;
        dcat[(long)(r0 + i) * C + c0 + tx] = __float2half(v);
    }
    __syncthreads();
    for (int i = ty; i < 32; i += 8)
        dallT[(long)(c0 + i) * dld + r0 + tx] = __float2half(tile[tx][i]);
}

// T[bh][z][s] = src0[b*Nc*ldk + s*ldk + h*64 + z]
__global__ __launch_bounds__(256) void ktrans_h(const __half* __restrict__ src0,
                                                int ldk, __half* __restrict__ KT)
{
    __shared__ __half tile[32][33];
    int s0 = blockIdx.x * 32, z0 = blockIdx.y * 32, bh = blockIdx.z;
    int b = bh / Hc, h = bh % Hc;
    int tx = threadIdx.x & 31, ty = threadIdx.x >> 5;
    const __half* src = src0 + (long)b * Nc * ldk + h * Zc;
    for (int i = ty; i < 32; i += 8)
        tile[i][tx] = src[(long)(s0 + i) * ldk + z0 + tx];
    __syncthreads();
    __half* dst = KT + (long)bh * Zc * Nc;
    for (int i = ty; i < 32; i += 8)
        dst[(long)(z0 + i) * Nc + s0 + tx] = tile[tx][i];
}

// ===========================================================================
template <int BM, int BN, int WM, int WN, int EPI>
static void run_h(const __half* A, const __half* B, void* C, void* C2,
                  int M, int N, int K, int lda, int ldb, int ldc)
{
    constexpr int SM = 3 * 2 * (BM + BN) * 32 * 2;
    cudaFuncSetAttribute(gemm_h<BM, BN, WM, WN, EPI>,
                         cudaFuncAttributeMaxDynamicSharedMemorySize, SM);
    dim3 grid(N / BN, M / BM);
    gemm_h<BM, BN, WM, WN, EPI>
        <<<grid, (BM / WM) * (BN / WN) * 32, SM>>>(A, B, C, C2, K, lda, ldb, ldc);
}

extern "C" void kernel_launch(void* const* d_in, const int* in_sizes, int n_in,
                              void* d_out, int out_size)
{
    const float* x     = (const float*)d_in[0];
    const float* Wq    = (const float*)d_in[1];
    const float* Wk    = (const float*)d_in[2];
    const float* betas = (const float*)d_in[3];
    const float* Wmlp  = (const float*)d_in[4];
    float* out = (float*)d_out;

    __half *QKh, *KTh, *QTh, *AVh, *xh, *WcatH, *WallTh;
    float *Zinv;
    cudaGetSymbolAddress((void**)&QKh,    g_QKh);
    cudaGetSymbolAddress((void**)&KTh,    g_KTh);
    cudaGetSymbolAddress((void**)&QTh,    g_QTh);
    cudaGetSymbolAddress((void**)&AVh,    g_AVh);
    cudaGetSymbolAddress((void**)&Zinv,   g_Zinv);
    cudaGetSymbolAddress((void**)&xh,     g_xh);
    cudaGetSymbolAddress((void**)&WcatH,  g_WcatH);
    cudaGetSymbolAddress((void**)&WallTh, g_WallTh);

    cudaFuncSetAttribute(fa_k<1>, cudaFuncAttributeMaxDynamicSharedMemorySize, fa::SMEM);
    cudaFuncSetAttribute(fa_k<0>, cudaFuncAttributeMaxDynamicSharedMemorySize, fa::SMEM);

    // ---- x -> half; weights -> (row-major half, transposed half) in one pass ----
    hconv_k<<<(Mrows * Dc / 4 + 255) / 256, 256>>>(x, xh, Mrows * Dc / 4);
    wprep_k<<<dim3(Dc / 32, Dc / 32), 256>>>(Wq, WcatH, WallTh, Dc, Dc, KC);
    wprep_k<<<dim3(Dc / 32, Dc / 32), 256>>>(Wk, WcatH + (size_t)Dc * Dc,
                                             WallTh + Dc, Dc, Dc, KC);
    wprep_k<<<dim3(Dc / 32, HIDc / 32), 256>>>(Wmlp, WcatH + (size_t)D2 * Dc,
                                               WallTh + D2, HIDc, Dc, KC);

    // 1) [Q|K|hid] = x @ Wcat^T  (one GEMM; hid -> AVh cols 1536:4608, relu)
    run_h<128, 128, 64, 64, E_PROJ>(xh, WcatH, QKh, AVh,
                                    Mrows, KC, Dc, Dc, Dc, 0);

    // Per-head transposes of K and Q (both plain; Zinv handled inside FA2)
    ktrans_h<<<dim3(Nc / 32, Zc / 32, Bc * Hc), 256>>>(QKh + Dc, D2, KTh);
    ktrans_h<<<dim3(Nc / 32, Zc / 32, Bc * Hc), 256>>>(QKh, D2, QTh);

    // 2) FA1: AV1 -> AVh[:,0:768], Zinv inline  (R=Q, C=K, T2=KT)
    fa_k<1><<<dim3(Nc / 64, Bc * Hc), 256, fa::SMEM>>>(
        QKh, D2, QKh + Dc, D2, KTh, AVh, KC, Zinv, betas);

    // 3) FA2: AV2 -> AVh[:,768:1536]  (R=K, C=Q, T2=QT, Zinv folded into exp)
    fa_k<0><<<dim3(Nc / 64, Bc * Hc), 256, fa::SMEM>>>(
        QKh + Dc, D2, QKh, D2, QTh, AVh + Dc, KC, Zinv, betas);

    // 4) out = [AV1|AV2|hid] @ Wall  (single K=4608 GEMM, fp32 out)
    run_h<128, 128, 64, 64, E_STOREF>(AVh, WallTh, out, nullptr,
                                      Mrows, Dc, KC, KC, KC, Dc);
}

// round 17
// speedup vs baseline: 1.0941x; 1.0941x over previous
#include <cuda_runtime.h>
#include <cuda_fp16.h>
#include <cstdint>

// ---------------------------------------------------------------------------
// KQEnergyBlock: B=8, N=1024, D=768, H=12, Z=64, HID=3072
//   [Q|K|hid] = x @ [Wq;Wk;Wmlp]^T  (ONE projection GEMM, epilogue routing)
//   FA1: S=Q K^T, Pu=exp(beta S) kept in REGISTERS (C->A fragment reuse),
//        AV1=Zinv*(Pu K), Zinv inline. FA2: symmetric, Zinv folded into exp.
//   out = [AV1|AV2|hid] @ [Wq;Wk;Wmlp]-stacked  (single K=4608 GEMM)
// R17 = R16 resubmit (infra failure last round; kernel re-audited vs PTX
// fragment layouts — C->A slot mapping, B key addressing, ring safety all ok).
// ---------------------------------------------------------------------------

namespace {
constexpr int Bc = 8, Nc = 1024, Dc = 768, Hc = 12, Zc = 64, HIDc = 3072;
constexpr int Mrows = Bc * Nc;    // 8192
constexpr int D2 = 2 * Dc;        // 1536
constexpr int KC = 2 * Dc + HIDc; // 4608
}

__device__ __align__(16) __half g_QKh[(size_t)Mrows * D2];      // [Q|K]
__device__ __align__(16) __half g_KTh[(size_t)Bc * Hc * Zc * Nc];
__device__ __align__(16) __half g_QTh[(size_t)Bc * Hc * Zc * Nc];
__device__ __align__(16) __half g_AVh[(size_t)Mrows * KC];      // [AV1|AV2|hid]
__device__ __align__(16) float  g_Zinv[(size_t)Bc * Hc * Nc];
__device__ __align__(16) __half g_xh[Mrows * Dc];
__device__ __align__(16) __half g_WcatH[(size_t)KC * Dc];       // rows: Wq|Wk|Wmlp
__device__ __align__(16) __half g_WallTh[(size_t)Dc * KC];      // [d][e|e'|h]

enum { E_STOREF = 0, E_PROJ = 1 };

__device__ __forceinline__ void cp_async16(void* smem_dst, const void* gmem_src) {
    uint32_t sa = (uint32_t)__cvta_generic_to_shared(smem_dst);
    asm volatile("cp.async.cg.shared.global [%0], [%1], 16;\n" :: "r"(sa), "l"(gmem_src));
}
__device__ __forceinline__ void cp_commit() {
    asm volatile("cp.async.commit_group;\n");
}
template <int Nw>
__device__ __forceinline__ void cp_wait() {
    asm volatile("cp.async.wait_group %0;\n" :: "n"(Nw));
}

__device__ __forceinline__ void mma_f16(float c[4],
                                        uint32_t a0, uint32_t a1, uint32_t a2, uint32_t a3,
                                        uint32_t b0, uint32_t b1) {
    asm volatile(
        "mma.sync.aligned.m16n8k16.row.col.f32.f16.f16.f32 "
        "{%0,%1,%2,%3}, {%4,%5,%6,%7}, {%8,%9}, {%0,%1,%2,%3};\n"
        : "+f"(c[0]), "+f"(c[1]), "+f"(c[2]), "+f"(c[3])
        : "r"(a0), "r"(a1), "r"(a2), "r"(a3), "r"(b0), "r"(b1));
}
__device__ __forceinline__ uint32_t packh2(float a, float b) {
    __half2 h = __floats2half2_rn(a, b);
    return *reinterpret_cast<uint32_t*>(&h);
}

// ===========================================================================
// fa_k v3: q-block 128, 256 threads (4 wq x 2 wk), register-resident P.
// smem: Rt 16K | Ct[4] 64K | T2[4] 64K | avred 32K | Zt 2K | red 1K | zs .5K
// ===========================================================================
namespace fa {
constexpr int OFF_R   = 0;
constexpr int OFF_C   = 16384;
constexpr int OFF_T2  = 81920;
constexpr int OFF_AVR = 147456;
constexpr int OFF_ZT  = 180224;
constexpr int OFF_RED = 182272;
constexpr int OFF_ZS  = 183296;
constexpr int SMEM    = 183808;
}

template <int DO_ZINV>
__global__ __launch_bounds__(256, 1)
void fa_k(const __half* __restrict__ Rbase, int ldr,
          const __half* __restrict__ Cbase, int ldcc,
          const __half* __restrict__ T2base, __half* __restrict__ Outbase,
          int ldo, float* __restrict__ zinvg, const float* __restrict__ betas)
{
    extern __shared__ __align__(16) char smem[];
    __half (*Rt)[128][32]     = reinterpret_cast<__half(*)[128][32]>(smem + fa::OFF_R);
    __half (*Ct)[2][128][32]  = reinterpret_cast<__half(*)[2][128][32]>(smem + fa::OFF_C);
    __half (*T2)[4][64][32]   = reinterpret_cast<__half(*)[4][64][32]>(smem + fa::OFF_T2);
    float (*avred)[32][64]    = reinterpret_cast<float(*)[32][64]>(smem + fa::OFF_AVR);
    float (*Zt)[128]          = reinterpret_cast<float(*)[128]>(smem + fa::OFF_ZT);
    float (*red)[128]         = reinterpret_cast<float(*)[128]>(smem + fa::OFF_RED);
    float* zs                 = reinterpret_cast<float*>(smem + fa::OFF_ZS);

    const int bh = blockIdx.y;
    const int b = bh / Hc, hi = bh % Hc;
    const int blk = blockIdx.x;
    const float beta = betas[hi];

    const __half* Rb = Rbase + ((long)b * Nc + blk * 128) * ldr + hi * Zc;
    const __half* Cb = Cbase + (long)b * Nc * ldcc + hi * Zc;
    const __half* T2b = T2base + (long)bh * Zc * Nc;
    __half* Outb = Outbase + ((long)b * Nc + blk * 128) * ldo + hi * Zc;

    const int tid = threadIdx.x;
    const int warp = tid >> 5;
    const int lane = tid & 31;
    const int group = lane >> 2;
    const int tg = lane & 3;
    const int wq = warp >> 1;   // 0..3 (q 32-row slice)
    const int wk = warp & 1;    // 0..1 (key 64-half)

    auto loadC = [&](int it2, int s) {
#pragma unroll
        for (int i = 0; i < 4; i++) {
            int c = tid + i * 256;
            int m = c >> 3, r = c & 7;
            int zc = r >> 2, q = r & 3;
            cp_async16(&Ct[s][zc][m][q * 8],
                       &Cb[(long)(it2 * 128 + m) * ldcc + zc * 32 + q * 8]);
        }
#pragma unroll
        for (int i = 0; i < 4; i++) {
            int c = tid + i * 256;
            int kc = c >> 8, rem = c & 255;
            int z = rem >> 2, q = rem & 3;
            cp_async16(&T2[s][kc][z][q * 8],
                       &T2b[(long)z * Nc + it2 * 128 + kc * 32 + q * 8]);
        }
        if (DO_ZINV == 0) {
            if (tid < 32)
                cp_async16(&Zt[s][tid * 4],
                           &zinvg[(long)bh * Nc + it2 * 128 + tid * 4]);
        }
        cp_commit();
    };

    {   // prefetch R block + stage0, then stage1
#pragma unroll
        for (int i = 0; i < 4; i++) {
            int c = tid + i * 256;
            int m = c >> 3, r = c & 7;
            int zc = r >> 2, q = r & 3;
            cp_async16(&Rt[zc][m][q * 8], &Rb[(long)m * ldr + zc * 32 + q * 8]);
        }
        loadC(0, 0);
        loadC(1, 1);
    }

    float av[2][8][4];            // [mt][z-tile][4]
#pragma unroll
    for (int i = 0; i < 2; i++)
#pragma unroll
        for (int j = 0; j < 8; j++)
#pragma unroll
            for (int r = 0; r < 4; r++) av[i][j][r] = 0.f;
    float rs[2][2];
    if (DO_ZINV) { rs[0][0] = rs[0][1] = rs[1][0] = rs[1][1] = 0.f; }

    for (int it = 0; it < 8; it++) {
        const int s = it & 3;
        if (it + 2 < 8) loadC(it + 2, (it + 2) & 3);
        else cp_commit();
        cp_wait<2>();
        __syncthreads();          // single sync per iteration (NST=4 ring)

        // ---- S(it) = R @ C^T  (warp tile 32q x 64k: this warp's key-half) ----
        float sacc[2][8][4];
#pragma unroll
        for (int i = 0; i < 2; i++)
#pragma unroll
            for (int j = 0; j < 8; j++)
#pragma unroll
                for (int r = 0; r < 4; r++) sacc[i][j][r] = 0.f;

#pragma unroll
        for (int zc = 0; zc < 2; zc++) {
            uint4 a[2][2];
#pragma unroll
            for (int mt = 0; mt < 2; mt++) {
                int mr = wq * 32 + mt * 16 + group;
                a[mt][0] = *reinterpret_cast<const uint4*>(&Rt[zc][mr][tg * 8]);
                a[mt][1] = *reinterpret_cast<const uint4*>(&Rt[zc][mr + 8][tg * 8]);
            }
#pragma unroll
            for (int nt = 0; nt < 8; nt++) {
                int nc = wk * 64 + nt * 8 + group;
                uint4 bb = *reinterpret_cast<const uint4*>(&Ct[s][zc][nc][tg * 8]);
#pragma unroll
                for (int mt = 0; mt < 2; mt++) {
                    mma_f16(sacc[mt][nt], a[mt][0].x, a[mt][1].x, a[mt][0].y, a[mt][1].y,
                            bb.x, bb.y);
                    mma_f16(sacc[mt][nt], a[mt][0].z, a[mt][1].z, a[mt][0].w, a[mt][1].w,
                            bb.z, bb.w);
                }
            }
        }

        // ---- exp in registers; pack into A-fragment halves ----
        uint32_t pu[2][8][2];
#pragma unroll
        for (int mt = 0; mt < 2; mt++) {
#pragma unroll
            for (int nt = 0; nt < 8; nt++) {
                float v0 = __expf(beta * sacc[mt][nt][0]);
                float v1 = __expf(beta * sacc[mt][nt][1]);
                float v2 = __expf(beta * sacc[mt][nt][2]);
                float v3 = __expf(beta * sacc[mt][nt][3]);
                if (DO_ZINV) {
                    rs[mt][0] += v0 + v1;   // row group
                    rs[mt][1] += v2 + v3;   // row group+8
                } else {
                    int col = wk * 64 + nt * 8 + tg * 2;   // physical streamed col
                    float z0 = Zt[s][col];
                    float z1 = Zt[s][col + 1];
                    v0 *= z0; v1 *= z1; v2 *= z0; v3 *= z1;
                }
                pu[mt][nt][0] = packh2(v0, v1);   // (row g,   keys nt*8+2tg..)
                pu[mt][nt][1] = packh2(v2, v3);   // (row g+8, same keys)
            }
        }

        // ---- AV partial += P_regs @ T2^T over this warp's 64 keys ----
#pragma unroll
        for (int kc = 0; kc < 4; kc++) {
            const int chunk = wk * 2 + (kc >> 1);
            const int koff = (kc & 1) * 16 + tg * 2;
#pragma unroll
            for (int znt = 0; znt < 8; znt++) {
                int zr = znt * 8 + group;
                uint32_t b0 = *reinterpret_cast<const uint32_t*>(&T2[s][chunk][zr][koff]);
                uint32_t b1 = *reinterpret_cast<const uint32_t*>(&T2[s][chunk][zr][koff + 8]);
#pragma unroll
                for (int mt = 0; mt < 2; mt++)
                    mma_f16(av[mt][znt],
                            pu[mt][2 * kc][0], pu[mt][2 * kc][1],
                            pu[mt][2 * kc + 1][0], pu[mt][2 * kc + 1][1],
                            b0, b1);
            }
        }
    }

    __syncthreads();   // all iters done; stages free for avred reuse

    // ---- Zinv (FA1): combine per-warp key-half rowsums ----
    if (DO_ZINV) {
#pragma unroll
        for (int mt = 0; mt < 2; mt++) {
#pragma unroll
            for (int h = 0; h < 2; h++) {
                float v = rs[mt][h];
                v += __shfl_xor_sync(0xffffffffu, v, 1);
                v += __shfl_xor_sync(0xffffffffu, v, 2);
                if (tg == 0)
                    red[wk][wq * 32 + mt * 16 + h * 8 + group] = v;
            }
        }
        __syncthreads();
        if (tid < 128) {
            float zi = 1.f / (red[0][tid] + red[1][tid]);
            zs[tid] = zi;
            zinvg[(long)bh * Nc + blk * 128 + tid] = zi;
        }
    }

    // ---- combine the two key-half AV partials; store ----
    if (wk == 1) {
#pragma unroll
        for (int mt = 0; mt < 2; mt++)
#pragma unroll
            for (int znt = 0; znt < 8; znt++)
#pragma unroll
                for (int h = 0; h < 2; h++) {
                    int rloc = mt * 16 + h * 8 + group;
                    float2 w;
                    w.x = av[mt][znt][h * 2 + 0];
                    w.y = av[mt][znt][h * 2 + 1];
                    *reinterpret_cast<float2*>(&avred[wq][rloc][znt * 8 + tg * 2]) = w;
                }
    }
    __syncthreads();
    if (wk == 0) {
#pragma unroll
        for (int mt = 0; mt < 2; mt++) {
#pragma unroll
            for (int znt = 0; znt < 8; znt++) {
#pragma unroll
                for (int h = 0; h < 2; h++) {
                    int rloc = mt * 16 + h * 8 + group;
                    float2 o = *reinterpret_cast<const float2*>(
                        &avred[wq][rloc][znt * 8 + tg * 2]);
                    float v0 = av[mt][znt][h * 2 + 0] + o.x;
                    float v1 = av[mt][znt][h * 2 + 1] + o.y;
                    int row = wq * 32 + rloc;
                    if (DO_ZINV) {
                        float zi = zs[row];
                        v0 *= zi; v1 *= zi;
                    }
                    *reinterpret_cast<__half2*>(
                        &Outb[(long)row * ldo + znt * 8 + tg * 2]) =
                        __floats2half2_rn(v0, v1);
                }
            }
        }
    }
}

// ===========================================================================
// Dense half GEMM, BK=64 chunked (R13, proven).
// ===========================================================================
template <int BM, int BN, int WM, int WN, int EPI>
__global__ __launch_bounds__((BM / WM) * (BN / WN) * 32)
void gemm_h(const __half* __restrict__ A, const __half* __restrict__ Bm,
            void* __restrict__ Cbase, void* __restrict__ C2base,
            int K, int lda, int ldb, int ldc)
{
    constexpr int NW = (BM / WM) * (BN / WN);
    constexpr int NT = NW * 32;
    constexpr int MT = WM / 16;
    constexpr int NTI = WN / 8;
    constexpr int NST = 3;
    constexpr int BK = 64;

    extern __shared__ __align__(16) __half dsm[];
    __half (*As)[2][BM][32] = reinterpret_cast<__half(*)[2][BM][32]>(dsm);
    __half (*Bs)[2][BN][32] =
        reinterpret_cast<__half(*)[2][BN][32]>(dsm + (size_t)NST * 2 * BM * 32);

    const int t = threadIdx.x;
    const int warp = t >> 5;
    const int lane = t & 31;
    const int group = lane >> 2;
    const int tg = lane & 3;
    const int wm = warp / (BN / WN);
    const int wn = warp % (BN / WN);
    const int m0 = blockIdx.y * BM;
    const int n0 = blockIdx.x * BN;

    const int nk = K / BK;

    auto prefetch = [&](int kt, int s) {
        const int k0 = kt * BK;
#pragma unroll
        for (int ch = 0; ch < 2; ch++) {
#pragma unroll
            for (int it = 0; it < (BM * 4) / NT; ++it) {
                int c = t + it * NT;
                int m = c >> 2, q = c & 3;
                cp_async16(&As[s][ch][m][q * 8],
                           &A[(long)(m0 + m) * lda + k0 + ch * 32 + q * 8]);
            }
#pragma unroll
            for (int it = 0; it < (BN * 4) / NT; ++it) {
                int c = t + it * NT;
                int n = c >> 2, q = c & 3;
                cp_async16(&Bs[s][ch][n][q * 8],
                           &Bm[(long)(n0 + n) * ldb + k0 + ch * 32 + q * 8]);
            }
        }
        cp_commit();
    };

    float acc[MT][NTI][4];
#pragma unroll
    for (int i = 0; i < MT; i++)
#pragma unroll
        for (int j = 0; j < NTI; j++)
#pragma unroll
            for (int r = 0; r < 4; r++) acc[i][j][r] = 0.f;

    prefetch(0, 0);
    if (nk > 1) prefetch(1, 1); else cp_commit();

    for (int kt = 0; kt < nk; kt++) {
        const int s = kt % NST;
        if (kt + 2 < nk) prefetch(kt + 2, (kt + 2) % NST);
        else cp_commit();
        cp_wait<2>();
        __syncthreads();

#pragma unroll
        for (int ch = 0; ch < 2; ch++) {
            uint4 a4[MT][2];
            uint4 b4[NTI];
#pragma unroll
            for (int mt = 0; mt < MT; mt++) {
                int mr = wm * WM + mt * 16 + group;
                a4[mt][0] = *reinterpret_cast<const uint4*>(&As[s][ch][mr][tg * 8]);
                a4[mt][1] = *reinterpret_cast<const uint4*>(&As[s][ch][mr + 8][tg * 8]);
            }
#pragma unroll
            for (int nt = 0; nt < NTI; nt++) {
                int nc = wn * WN + nt * 8 + group;
                b4[nt] = *reinterpret_cast<const uint4*>(&Bs[s][ch][nc][tg * 8]);
            }
#pragma unroll
            for (int mt = 0; mt < MT; mt++)
#pragma unroll
                for (int nt = 0; nt < NTI; nt++)
                    mma_f16(acc[mt][nt], a4[mt][0].x, a4[mt][1].x, a4[mt][0].y, a4[mt][1].y,
                            b4[nt].x, b4[nt].y);
#pragma unroll
            for (int mt = 0; mt < MT; mt++)
#pragma unroll
                for (int nt = 0; nt < NTI; nt++)
                    mma_f16(acc[mt][nt], a4[mt][0].z, a4[mt][1].z, a4[mt][0].w, a4[mt][1].w,
                            b4[nt].z, b4[nt].w);
        }
        __syncthreads();
    }

#pragma unroll
    for (int mt = 0; mt < MT; mt++) {
#pragma unroll
        for (int nt = 0; nt < NTI; nt++) {
            int gm = m0 + wm * WM + mt * 16 + group;
            int gn = n0 + wn * WN + nt * 8 + tg * 2;
#pragma unroll
            for (int half = 0; half < 2; half++) {
                int row = gm + half * 8;
                float v0 = acc[mt][nt][half * 2 + 0];
                float v1 = acc[mt][nt][half * 2 + 1];
                if (EPI == E_PROJ) {
                    if (gn < D2) {
                        __half* C = (__half*)Cbase;
                        *reinterpret_cast<__half2*>(&C[(long)row * D2 + gn]) =
                            __floats2half2_rn(v0, v1);
                    } else {
                        v0 = fmaxf(v0, 0.f); v1 = fmaxf(v1, 0.f);
                        __half* C2 = (__half*)C2base;
                        *reinterpret_cast<__half2*>(&C2[(long)row * KC + gn]) =
                            __floats2half2_rn(v0, v1);
                    }
                } else {
                    float* C = (float*)Cbase;
                    float2 w; w.x = v0; w.y = v1;
                    *reinterpret_cast<float2*>(&C[(long)row * ldc + gn]) = w;
                }
            }
        }
    }
}

// ===========================================================================
// Pre-pass kernels
// ===========================================================================
__global__ __launch_bounds__(256) void hconv_k(const float* __restrict__ src,
                                               __half* __restrict__ dst, long n4)
{
    long i = (long)blockIdx.x * 256 + threadIdx.x;
    if (i >= n4) return;
    float4 v = reinterpret_cast<const float4*>(src)[i];
    __half2 h0 = __floats2half2_rn(v.x, v.y);
    __half2 h1 = __floats2half2_rn(v.z, v.w);
    uint2 u;
    u.x = *reinterpret_cast<uint32_t*>(&h0);
    u.y = *reinterpret_cast<uint32_t*>(&h1);
    reinterpret_cast<uint2*>(dst)[i] = u;
}

__global__ __launch_bounds__(256) void wprep_k(const float* __restrict__ src,
                                               __half* __restrict__ dcat,
                                               __half* __restrict__ dallT,
                                               int R, int C, int dld)
{
    __shared__ float tile[32][33];
    int c0 = blockIdx.x * 32, r0 = blockIdx.y * 32;
    int tx = threadIdx.x & 31, ty = threadIdx.x >> 5;
    for (int i = ty; i < 32; i += 8) {
        float v = src[(long)(r0 + i) * C + c0 + tx];
        tile[i][tx] = v;
        dcat[(long)(r0 + i) * C + c0 + tx] = __float2half(v);
    }
    __syncthreads();
    for (int i = ty; i < 32; i += 8)
        dallT[(long)(c0 + i) * dld + r0 + tx] = __float2half(tile[tx][i]);
}

__global__ __launch_bounds__(256) void ktrans_h(const __half* __restrict__ src0,
                                                int ldk, __half* __restrict__ KT)
{
    __shared__ __half tile[32][33];
    int s0 = blockIdx.x * 32, z0 = blockIdx.y * 32, bh = blockIdx.z;
    int b = bh / Hc, h = bh % Hc;
    int tx = threadIdx.x & 31, ty = threadIdx.x >> 5;
    const __half* src = src0 + (long)b * Nc * ldk + h * Zc;
    for (int i = ty; i < 32; i += 8)
        tile[i][tx] = src[(long)(s0 + i) * ldk + z0 + tx];
    __syncthreads();
    __half* dst = KT + (long)bh * Zc * Nc;
    for (int i = ty; i < 32; i += 8)
        dst[(long)(z0 + i) * Nc + s0 + tx] = tile[tx][i];
}

// ===========================================================================
template <int BM, int BN, int WM, int WN, int EPI>
static void run_h(const __half* A, const __half* B, void* C, void* C2,
                  int M, int N, int K, int lda, int ldb, int ldc)
{
    constexpr int SM = 3 * 2 * (BM + BN) * 32 * 2;
    cudaFuncSetAttribute(gemm_h<BM, BN, WM, WN, EPI>,
                         cudaFuncAttributeMaxDynamicSharedMemorySize, SM);
    dim3 grid(N / BN, M / BM);
    gemm_h<BM, BN, WM, WN, EPI>
        <<<grid, (BM / WM) * (BN / WN) * 32, SM>>>(A, B, C, C2, K, lda, ldb, ldc);
}

extern "C" void kernel_launch(void* const* d_in, const int* in_sizes, int n_in,
                              void* d_out, int out_size)
{
    const float* x     = (const float*)d_in[0];
    const float* Wq    = (const float*)d_in[1];
    const float* Wk    = (const float*)d_in[2];
    const float* betas = (const float*)d_in[3];
    const float* Wmlp  = (const float*)d_in[4];
    float* out = (float*)d_out;

    __half *QKh, *KTh, *QTh, *AVh, *xh, *WcatH, *WallTh;
    float *Zinv;
    cudaGetSymbolAddress((void**)&QKh,    g_QKh);
    cudaGetSymbolAddress((void**)&KTh,    g_KTh);
    cudaGetSymbolAddress((void**)&QTh,    g_QTh);
    cudaGetSymbolAddress((void**)&AVh,    g_AVh);
    cudaGetSymbolAddress((void**)&Zinv,   g_Zinv);
    cudaGetSymbolAddress((void**)&xh,     g_xh);
    cudaGetSymbolAddress((void**)&WcatH,  g_WcatH);
    cudaGetSymbolAddress((void**)&WallTh, g_WallTh);

    cudaFuncSetAttribute(fa_k<1>, cudaFuncAttributeMaxDynamicSharedMemorySize, fa::SMEM);
    cudaFuncSetAttribute(fa_k<0>, cudaFuncAttributeMaxDynamicSharedMemorySize, fa::SMEM);

    // ---- x -> half; weights -> (row-major half, transposed half) in one pass ----
    hconv_k<<<(Mrows * Dc / 4 + 255) / 256, 256>>>(x, xh, Mrows * Dc / 4);
    wprep_k<<<dim3(Dc / 32, Dc / 32), 256>>>(Wq, WcatH, WallTh, Dc, Dc, KC);
    wprep_k<<<dim3(Dc / 32, Dc / 32), 256>>>(Wk, WcatH + (size_t)Dc * Dc,
                                             WallTh + Dc, Dc, Dc, KC);
    wprep_k<<<dim3(Dc / 32, HIDc / 32), 256>>>(Wmlp, WcatH + (size_t)D2 * Dc,
                                               WallTh + D2, HIDc, Dc, KC);

    // 1) [Q|K|hid] = x @ Wcat^T  (one GEMM; hid -> AVh cols 1536:4608, relu)
    run_h<128, 128, 64, 64, E_PROJ>(xh, WcatH, QKh, AVh,
                                    Mrows, KC, Dc, Dc, Dc, 0);

    // Per-head transposes of K and Q
    ktrans_h<<<dim3(Nc / 32, Zc / 32, Bc * Hc), 256>>>(QKh + Dc, D2, KTh);
    ktrans_h<<<dim3(Nc / 32, Zc / 32, Bc * Hc), 256>>>(QKh, D2, QTh);

    // 2) FA1: AV1 -> AVh[:,0:768], Zinv inline  (R=Q, C=K, T2=KT)
    fa_k<1><<<dim3(Nc / 128, Bc * Hc), 256, fa::SMEM>>>(
        QKh, D2, QKh + Dc, D2, KTh, AVh, KC, Zinv, betas);

    // 3) FA2: AV2 -> AVh[:,768:1536]  (R=K, C=Q, T2=QT, Zinv folded into exp)
    fa_k<0><<<dim3(Nc / 128, Bc * Hc), 256, fa::SMEM>>>(
        QKh + Dc, D2, QKh, D2, QTh, AVh + Dc, KC, Zinv, betas);

    // 4) out = [AV1|AV2|hid] @ Wall  (single K=4608 GEMM, fp32 out)
    run_h<128, 128, 64, 64, E_STOREF>(AVh, WallTh, out, nullptr,
                                      Mrows, Dc, KC, KC, KC, Dc);
}